// round 12
// baseline (speedup 1.0000x reference)
#include <cuda_runtime.h>
#include <cuda_fp16.h>
#include <stdint.h>

#define NB 8      // batch
#define TT 8      // time (slice t = TT/2)
#define V  512    // nodes
#define F  64     // features
#define KP 32     // feature pairs
#define BLK 64    // tile edge
#define NBLK 8    // V/BLK
#define NPAIR 36  // NBLK*(NBLK+1)/2
#define TPB 256
#define NCTAS (NPAIR * NB)   // 288 == 2 per SM on 148 SMs (co-resident)

// colpartial[n][row-block b][column j] = sum over i-in-block-b of tmpS[i][j].
// Each entry has exactly one writer CTA -> no atomics, deterministic.
__device__ float g_colpartial[NB][NBLK][V];
// device-wide barrier state (reset to 0 by last CTA each launch -> replay-safe)
__device__ int g_arrive;
__device__ int g_flag;
__device__ int g_done;

__global__ __launch_bounds__(TPB, 2)
void fused_kernel(const float* __restrict__ x,
                  const float* __restrict__ a,
                  float* __restrict__ out) {
    __shared__ __half    yrow[2 * BLK][72];   // fp16 staging (144B rows)
    __shared__ uint32_t  y2[KP][2 * BLK];     // feature-major half2
    __shared__ float     cpart[2][BLK];
    __shared__ float     rpart[4][BLK];
    __shared__ __half2   sa2[KP];
    __shared__ float     sinv_p[BLK];         // 1/colsum for p-block columns
    __shared__ float     sinv_q[BLK];         // 1/colsum for q-block columns

    const int n   = blockIdx.y;
    int p = 0, rem = blockIdx.x;              // decode pair (p <= q)
    while (rem > (NBLK - 1) - p) { rem -= NBLK - p; p++; }
    const int q = p + rem;

    const int tid  = threadIdx.x;
    const int lane = tid & 31, wid = tid >> 5;
    const int r    = lane >> 2, c = lane & 3; // thread 4i x 4j
    const int wy   = wid >> 2,  wx = wid & 3; // warp 32i x 16j

    // ---- load i-block and j-block as fp16 ----
    const float4* xg = (const float4*)(x + ((size_t)n * TT + TT / 2) * V * F);
    for (int it = 0; it < 8; it++) {
        int idx = it * TPB + tid;
        int v = idx >> 4, ch = idx & 15;
        int src = (v < BLK) ? (BLK * p + v) : (BLK * q + (v - BLK));
        float4 w = xg[(size_t)src * 16 + ch];
        *(__half2*)&yrow[v][ch * 4]     = __float22half2_rn(make_float2(w.x, w.y));
        *(__half2*)&yrow[v][ch * 4 + 2] = __float22half2_rn(make_float2(w.z, w.w));
    }
    if (tid < KP) sa2[tid] = __float22half2_rn(make_float2(a[2 * tid], a[2 * tid + 1]));
    __syncthreads();

    // ---- transpose to feature-major ----
#pragma unroll
    for (int m = 0; m < 4; m++) {
        int u  = wid * 4 + m;
        int kc = u >> 2, vg = u & 3;
        int v  = vg * 32 + lane;
        uint4 w = *(const uint4*)&yrow[v][kc * 8];
        y2[4 * kc + 0][v] = w.x;
        y2[4 * kc + 1][v] = w.y;
        y2[4 * kc + 2][v] = w.z;
        y2[4 * kc + 3][v] = w.w;
    }
    __syncthreads();

    const int is0 = 32 * wy + 4 * r;
    const int js0 = 16 * wx + 4 * c;
    const __half2 z = __float2half2_rn(0.0f);
    __half2 acc0[16], acc1[16];
#pragma unroll
    for (int pp = 0; pp < 16; pp++) { acc0[pp] = z; acc1[pp] = z; }

    // ---- main loop: two 16-k fp16 banks ----
#pragma unroll 1
    for (int bank = 0; bank < 2; bank++) {
        __half2* acc = bank ? acc1 : acc0;
#pragma unroll 4
        for (int k8 = 0; k8 < 16; k8++) {
            const int k = bank * 16 + k8;
            uint4 iw = *(const uint4*)&y2[k][is0];
            uint4 jw = *(const uint4*)&y2[k][BLK + js0];
            __half2 ifr[4] = {*(__half2*)&iw.x, *(__half2*)&iw.y,
                              *(__half2*)&iw.z, *(__half2*)&iw.w};
            __half2 jfr[4] = {*(__half2*)&jw.x, *(__half2*)&jw.y,
                              *(__half2*)&jw.z, *(__half2*)&jw.w};
            __half2 ak = sa2[k];
#pragma unroll
            for (int ii = 0; ii < 4; ii++)
#pragma unroll
                for (int jj = 0; jj < 4; jj++) {
                    __half2 d = __habs2(__hsub2(ifr[ii], jfr[jj]));
                    acc[ii * 4 + jj] = __hfma2(d, ak, acc[ii * 4 + jj]);
                }
        }
    }

    // ---- tmpS tile (kept in registers through the barrier) ----
    float t[16];
#pragma unroll
    for (int pp = 0; pp < 16; pp++) {
        float2 f = __half22float2(acc0[pp]);
        float2 g = __half22float2(acc1[pp]);
        float s  = (f.x + f.y) + (g.x + g.y);
        t[pp] = __expf(fmaxf(s, 0.0f));
    }

    // ---- column sums over tile-i (q-block columns) ----
    float cs[4];
#pragma unroll
    for (int jj = 0; jj < 4; jj++)
        cs[jj] = (t[0 * 4 + jj] + t[1 * 4 + jj]) + (t[2 * 4 + jj] + t[3 * 4 + jj]);
#pragma unroll
    for (int m = 4; m <= 16; m <<= 1)
#pragma unroll
        for (int jj = 0; jj < 4; jj++)
            cs[jj] += __shfl_xor_sync(0xFFFFFFFFu, cs[jj], m);
    if (r == 0)
#pragma unroll
        for (int jj = 0; jj < 4; jj++)
            cpart[wy][16 * wx + 4 * c + jj] = cs[jj];

    // ---- row sums over tile-j (p-block columns) ----
    float rs[4];
#pragma unroll
    for (int ii = 0; ii < 4; ii++)
        rs[ii] = (t[ii * 4 + 0] + t[ii * 4 + 1]) + (t[ii * 4 + 2] + t[ii * 4 + 3]);
#pragma unroll
    for (int m = 1; m <= 2; m <<= 1)
#pragma unroll
        for (int ii = 0; ii < 4; ii++)
            rs[ii] += __shfl_xor_sync(0xFFFFFFFFu, rs[ii], m);
    if (c == 0)
#pragma unroll
        for (int ii = 0; ii < 4; ii++)
            rpart[wx][32 * wy + 4 * r + ii] = rs[ii];
    __syncthreads();

    if (tid < BLK) {
        g_colpartial[n][p][BLK * q + tid] = cpart[0][tid] + cpart[1][tid];
        if (p != q)
            g_colpartial[n][q][BLK * p + tid] =
                (rpart[0][tid] + rpart[1][tid]) + (rpart[2][tid] + rpart[3][tid]);
    }

    // ================= device-wide barrier (288 co-resident CTAs) =================
    __threadfence();                       // publish partials
    __syncthreads();
    if (tid == 0) {
        int old = atomicAdd(&g_arrive, 1);
        if (old == NCTAS - 1) {
            __threadfence();
            atomicExch(&g_flag, 1);        // release
        }
        while (atomicAdd(&g_flag, 0) == 0) __nanosleep(64);   // acquire spin
    }
    __syncthreads();
    __threadfence();                       // acquire: see all partials

    // ---- rebuild column sums for this CTA's 128 columns (L2-resident reads) ----
    if (tid < BLK) {
        float s = 0.0f;
#pragma unroll
        for (int b = 0; b < NBLK; b++) s += g_colpartial[n][b][BLK * q + tid];
        sinv_q[tid] = 1.0f / s;
    } else if (tid < 2 * BLK) {
        int jj = tid - BLK;
        float s = 0.0f;
#pragma unroll
        for (int b = 0; b < NBLK; b++) s += g_colpartial[n][b][BLK * p + jj];
        sinv_p[jj] = 1.0f / s;
    }
    __syncthreads();

    // ---- normalize + single write of out (direct tile + transpose tile) ----
    float* on = out + (size_t)n * V * V;
    const int gi0 = BLK * p + is0;
    const int gj0 = BLK * q + js0;
    const float4 invq = *(const float4*)&sinv_q[js0];
#pragma unroll
    for (int ii = 0; ii < 4; ii++) {
        float4 o = make_float4(t[ii * 4 + 0] * invq.x, t[ii * 4 + 1] * invq.y,
                               t[ii * 4 + 2] * invq.z, t[ii * 4 + 3] * invq.w);
        *(float4*)(on + (size_t)(gi0 + ii) * V + gj0) = o;
    }
    const float4 invp = *(const float4*)&sinv_p[is0];
#pragma unroll
    for (int jj = 0; jj < 4; jj++) {
        float4 o = make_float4(t[0 * 4 + jj] * invp.x, t[1 * 4 + jj] * invp.y,
                               t[2 * 4 + jj] * invp.z, t[3 * 4 + jj] * invp.w);
        *(float4*)(on + (size_t)(gj0 + jj) * V + gi0) = o;
    }

    // ---- barrier state reset by the last CTA to finish (replay-safe) ----
    __syncthreads();
    if (tid == 0) {
        int old = atomicAdd(&g_done, 1);
        if (old == NCTAS - 1) {
            g_arrive = 0;
            g_flag   = 0;
            g_done   = 0;
            __threadfence();
        }
    }
}

extern "C" void kernel_launch(void* const* d_in, const int* in_sizes, int n_in,
                              void* d_out, int out_size) {
    const float* x = (const float*)d_in[0];
    const float* a = (const float*)d_in[1];
    if (n_in >= 2 && in_sizes[0] == F && in_sizes[1] == NB * TT * V * F) {
        const float* t = x; x = a; a = t;
    }
    float* out = (float*)d_out;

    dim3 g1(NPAIR, NB);   // 288 CTAs: 2/SM co-resident via __launch_bounds__(256,2)
    fused_kernel<<<g1, TPB>>>(x, a, out);
}

// round 13
// speedup vs baseline: 1.0035x; 1.0035x over previous
#include <cuda_runtime.h>
#include <cuda_fp16.h>
#include <stdint.h>

#define NB 8      // batch
#define TT 8      // time (slice t = TT/2)
#define V  512    // nodes
#define F  64     // features
#define KP 32     // feature pairs
#define BLK 64    // tile edge
#define NBLK 8    // V/BLK
#define NPAIR 36  // NBLK*(NBLK+1)/2
#define TPB 256
#define NCTAS (NPAIR * NB)   // 288 == 2 per SM on 148 SMs (co-resident)

// colpartial[n][row-block b][column j] = sum over i-in-block-b of tmpS[i][j].
// Each entry has exactly one writer CTA -> no atomics, deterministic.
__device__ float g_colpartial[NB][NBLK][V];
// device-wide barrier state (reset to 0 by last CTA each launch -> replay-safe)
__device__ int g_arrive;
__device__ int g_flag;
__device__ int g_done;

__global__ __launch_bounds__(TPB, 2)
void fused_kernel(const float* __restrict__ x,
                  const float* __restrict__ a,
                  float* __restrict__ out) {
    __shared__ __half    yrow[2 * BLK][72];   // fp16 staging (144B rows)
    __shared__ uint32_t  y2[KP][2 * BLK];     // feature-major half2
    __shared__ float     cpart[2][BLK];
    __shared__ float     rpart[4][BLK];
    __shared__ __half2   sa2[KP];
    __shared__ float     sinv_p[BLK];         // 1/colsum for p-block columns
    __shared__ float     sinv_q[BLK];         // 1/colsum for q-block columns

    const int n   = blockIdx.y;
    int p = 0, rem = blockIdx.x;              // decode pair (p <= q)
    while (rem > (NBLK - 1) - p) { rem -= NBLK - p; p++; }
    const int q = p + rem;

    const int tid  = threadIdx.x;
    const int lane = tid & 31, wid = tid >> 5;
    const int r    = lane >> 2, c = lane & 3; // thread 4i x 4j
    const int wy   = wid >> 2,  wx = wid & 3; // warp 32i x 16j

    // ---- load i-block and j-block as fp16 ----
    const float4* xg = (const float4*)(x + ((size_t)n * TT + TT / 2) * V * F);
    for (int it = 0; it < 8; it++) {
        int idx = it * TPB + tid;
        int v = idx >> 4, ch = idx & 15;
        int src = (v < BLK) ? (BLK * p + v) : (BLK * q + (v - BLK));
        float4 w = xg[(size_t)src * 16 + ch];
        *(__half2*)&yrow[v][ch * 4]     = __float22half2_rn(make_float2(w.x, w.y));
        *(__half2*)&yrow[v][ch * 4 + 2] = __float22half2_rn(make_float2(w.z, w.w));
    }
    if (tid < KP) sa2[tid] = __float22half2_rn(make_float2(a[2 * tid], a[2 * tid + 1]));
    __syncthreads();

    // ---- transpose to feature-major ----
#pragma unroll
    for (int m = 0; m < 4; m++) {
        int u  = wid * 4 + m;
        int kc = u >> 2, vg = u & 3;
        int v  = vg * 32 + lane;
        uint4 w = *(const uint4*)&yrow[v][kc * 8];
        y2[4 * kc + 0][v] = w.x;
        y2[4 * kc + 1][v] = w.y;
        y2[4 * kc + 2][v] = w.z;
        y2[4 * kc + 3][v] = w.w;
    }
    __syncthreads();

    const int is0 = 32 * wy + 4 * r;
    const int js0 = 16 * wx + 4 * c;
    const __half2 z = __float2half2_rn(0.0f);
    __half2 acc0[16], acc1[16];
#pragma unroll
    for (int pp = 0; pp < 16; pp++) { acc0[pp] = z; acc1[pp] = z; }

    // ---- main loop: two 16-k fp16 banks ----
#pragma unroll 1
    for (int bank = 0; bank < 2; bank++) {
        __half2* acc = bank ? acc1 : acc0;
#pragma unroll 4
        for (int k8 = 0; k8 < 16; k8++) {
            const int k = bank * 16 + k8;
            uint4 iw = *(const uint4*)&y2[k][is0];
            uint4 jw = *(const uint4*)&y2[k][BLK + js0];
            __half2 ifr[4] = {*(__half2*)&iw.x, *(__half2*)&iw.y,
                              *(__half2*)&iw.z, *(__half2*)&iw.w};
            __half2 jfr[4] = {*(__half2*)&jw.x, *(__half2*)&jw.y,
                              *(__half2*)&jw.z, *(__half2*)&jw.w};
            __half2 ak = sa2[k];
#pragma unroll
            for (int ii = 0; ii < 4; ii++)
#pragma unroll
                for (int jj = 0; jj < 4; jj++) {
                    __half2 d = __habs2(__hsub2(ifr[ii], jfr[jj]));
                    acc[ii * 4 + jj] = __hfma2(d, ak, acc[ii * 4 + jj]);
                }
        }
    }

    // ---- tmpS tile (kept in registers through the barrier) ----
    float t[16];
#pragma unroll
    for (int pp = 0; pp < 16; pp++) {
        float2 f = __half22float2(acc0[pp]);
        float2 g = __half22float2(acc1[pp]);
        float s  = (f.x + f.y) + (g.x + g.y);
        t[pp] = __expf(fmaxf(s, 0.0f));
    }

    // ---- column sums over tile-i (q-block columns) ----
    float cs[4];
#pragma unroll
    for (int jj = 0; jj < 4; jj++)
        cs[jj] = (t[0 * 4 + jj] + t[1 * 4 + jj]) + (t[2 * 4 + jj] + t[3 * 4 + jj]);
#pragma unroll
    for (int m = 4; m <= 16; m <<= 1)
#pragma unroll
        for (int jj = 0; jj < 4; jj++)
            cs[jj] += __shfl_xor_sync(0xFFFFFFFFu, cs[jj], m);
    if (r == 0)
#pragma unroll
        for (int jj = 0; jj < 4; jj++)
            cpart[wy][16 * wx + 4 * c + jj] = cs[jj];

    // ---- row sums over tile-j (p-block columns) ----
    float rs[4];
#pragma unroll
    for (int ii = 0; ii < 4; ii++)
        rs[ii] = (t[ii * 4 + 0] + t[ii * 4 + 1]) + (t[ii * 4 + 2] + t[ii * 4 + 3]);
#pragma unroll
    for (int m = 1; m <= 2; m <<= 1)
#pragma unroll
        for (int ii = 0; ii < 4; ii++)
            rs[ii] += __shfl_xor_sync(0xFFFFFFFFu, rs[ii], m);
    if (c == 0)
#pragma unroll
        for (int ii = 0; ii < 4; ii++)
            rpart[wx][32 * wy + 4 * r + ii] = rs[ii];
    __syncthreads();

    if (tid < BLK) {
        g_colpartial[n][p][BLK * q + tid] = cpart[0][tid] + cpart[1][tid];
        if (p != q)
            g_colpartial[n][q][BLK * p + tid] =
                (rpart[0][tid] + rpart[1][tid]) + (rpart[2][tid] + rpart[3][tid]);
    }

    // ========== device-wide barrier: atomic arrive, LOAD-ONLY spin ==========
    // (R12 spun on atomicAdd(&g_flag,0): every poll is an L2 RMW serializing
    //  ~30cyc/op per address -> 287 spinners jam the line and delay the
    //  release itself. Poll with ld.acquire.gpu instead: read-only, no LTS
    //  atomic-ALU serialization.)
    __threadfence();                       // publish partials
    __syncthreads();
    if (tid == 0) {
        int old = atomicAdd(&g_arrive, 1);
        if (old == NCTAS - 1) {
            atomicExch(&g_flag, 1);        // release (fence above orders partials)
        } else {
            unsigned v;
            do {
                asm volatile("ld.acquire.gpu.global.u32 %0, [%1];"
                             : "=r"(v) : "l"(&g_flag));
                if (!v) __nanosleep(128);
            } while (!v);
        }
    }
    __syncthreads();
    __threadfence();                       // order post-barrier reads

    // ---- rebuild column sums for this CTA's 128 columns (L2-resident reads) ----
    if (tid < BLK) {
        float s = 0.0f;
#pragma unroll
        for (int b = 0; b < NBLK; b++) s += g_colpartial[n][b][BLK * q + tid];
        sinv_q[tid] = 1.0f / s;
    } else if (tid < 2 * BLK) {
        int jj = tid - BLK;
        float s = 0.0f;
#pragma unroll
        for (int b = 0; b < NBLK; b++) s += g_colpartial[n][b][BLK * p + jj];
        sinv_p[jj] = 1.0f / s;
    }
    __syncthreads();

    // ---- normalize + single write of out (direct tile + transpose tile) ----
    float* on = out + (size_t)n * V * V;
    const int gi0 = BLK * p + is0;
    const int gj0 = BLK * q + js0;
    const float4 invq = *(const float4*)&sinv_q[js0];
#pragma unroll
    for (int ii = 0; ii < 4; ii++) {
        float4 o = make_float4(t[ii * 4 + 0] * invq.x, t[ii * 4 + 1] * invq.y,
                               t[ii * 4 + 2] * invq.z, t[ii * 4 + 3] * invq.w);
        *(float4*)(on + (size_t)(gi0 + ii) * V + gj0) = o;
    }
    const float4 invp = *(const float4*)&sinv_p[is0];
#pragma unroll
    for (int jj = 0; jj < 4; jj++) {
        float4 o = make_float4(t[0 * 4 + jj] * invp.x, t[1 * 4 + jj] * invp.y,
                               t[2 * 4 + jj] * invp.z, t[3 * 4 + jj] * invp.w);
        *(float4*)(on + (size_t)(gj0 + jj) * V + gi0) = o;
    }

    // ---- barrier state reset by the last CTA to finish (replay-safe) ----
    __syncthreads();
    if (tid == 0) {
        int old = atomicAdd(&g_done, 1);
        if (old == NCTAS - 1) {
            g_arrive = 0;
            g_flag   = 0;
            g_done   = 0;
            __threadfence();
        }
    }
}

extern "C" void kernel_launch(void* const* d_in, const int* in_sizes, int n_in,
                              void* d_out, int out_size) {
    const float* x = (const float*)d_in[0];
    const float* a = (const float*)d_in[1];
    if (n_in >= 2 && in_sizes[0] == F && in_sizes[1] == NB * TT * V * F) {
        const float* t = x; x = a; a = t;
    }
    float* out = (float*)d_out;

    dim3 g1(NPAIR, NB);   // 288 CTAs: 2/SM co-resident via __launch_bounds__(256,2)
    fused_kernel<<<g1, TPB>>>(x, a, out);
}

// round 15
// speedup vs baseline: 1.1267x; 1.1228x over previous
#include <cuda_runtime.h>
#include <cuda_fp16.h>
#include <stdint.h>

#define NB 8      // batch
#define TT 8      // time (slice t = TT/2)
#define V  512    // nodes
#define F  64     // features
#define KP 32     // feature pairs
#define BLK 64    // tile edge
#define NBLK 8    // V/BLK
#define NPAIR 36  // NBLK*(NBLK+1)/2
#define TPB 256
#define NCTAS (NPAIR * NB)   // 288 == 2 per SM (co-resident via launch_bounds)

// colpartial[n][row-block b][column j] = sum over i-in-block-b of tmpS[i][j].
// Exactly one writer per entry -> no atomics, deterministic.
__device__ float g_colpartial[NB][NBLK][V];
// device-wide barrier state (reset by last CTA each launch -> replay-safe)
__device__ int g_arrive;
__device__ int g_flag;
__device__ int g_done;

__global__ __launch_bounds__(TPB, 2)
void fused_kernel(const float* __restrict__ x,
                  const float* __restrict__ a,
                  float* __restrict__ out) {
    __shared__ __half    yrow[2 * BLK][72];   // fp16 staging (144B rows)
    __shared__ uint32_t  y2[KP][2 * BLK];     // feature-major half2
    __shared__ float     cpart[2][BLK];
    __shared__ float     rpart[4][BLK];
    __shared__ __half2   sa2[KP];
    __shared__ float     sinv_p[BLK];
    __shared__ float     sinv_q[BLK];

    const int n   = blockIdx.y;
    int p = 0, rem = blockIdx.x;              // decode pair (p <= q)
    while (rem > (NBLK - 1) - p) { rem -= NBLK - p; p++; }
    const int q = p + rem;

    const int tid  = threadIdx.x;
    const int lane = tid & 31, wid = tid >> 5;
    const int r    = lane >> 2, c = lane & 3; // thread 4i x 4j
    const int wy   = wid >> 2,  wx = wid & 3; // warp 32i x 16j

    // ---- load i-block and j-block as fp16 ----
    const float4* xg = (const float4*)(x + ((size_t)n * TT + TT / 2) * V * F);
    for (int it = 0; it < 8; it++) {
        int idx = it * TPB + tid;
        int v = idx >> 4, ch = idx & 15;
        int src = (v < BLK) ? (BLK * p + v) : (BLK * q + (v - BLK));
        float4 w = xg[(size_t)src * 16 + ch];
        *(__half2*)&yrow[v][ch * 4]     = __float22half2_rn(make_float2(w.x, w.y));
        *(__half2*)&yrow[v][ch * 4 + 2] = __float22half2_rn(make_float2(w.z, w.w));
    }
    if (tid < KP) sa2[tid] = __float22half2_rn(make_float2(a[2 * tid], a[2 * tid + 1]));
    __syncthreads();

    // ---- transpose to feature-major ----
#pragma unroll
    for (int m = 0; m < 4; m++) {
        int u  = wid * 4 + m;
        int kc = u >> 2, vg = u & 3;
        int v  = vg * 32 + lane;
        uint4 w = *(const uint4*)&yrow[v][kc * 8];
        y2[4 * kc + 0][v] = w.x;
        y2[4 * kc + 1][v] = w.y;
        y2[4 * kc + 2][v] = w.z;
        y2[4 * kc + 3][v] = w.w;
    }
    __syncthreads();

    const int is0 = 32 * wy + 4 * r;
    const int js0 = 16 * wx + 4 * c;
    const __half2 z = __float2half2_rn(0.0f);
    __half2 acc0[16], acc1[16];
#pragma unroll
    for (int pp = 0; pp < 16; pp++) { acc0[pp] = z; acc1[pp] = z; }

    // ---- main loop: FULLY UNROLLED k, static bank select (acc stays in
    // registers — no runtime pointer), 1-deep fragment prefetch ----
    uint4 iw = *(const uint4*)&y2[0][is0];
    uint4 jw = *(const uint4*)&y2[0][BLK + js0];
#pragma unroll
    for (int k = 0; k < KP; k++) {
        uint4 iwn, jwn;
        if (k + 1 < KP) {
            iwn = *(const uint4*)&y2[k + 1][is0];
            jwn = *(const uint4*)&y2[k + 1][BLK + js0];
        }
        const __half2 ak = sa2[k];
        __half2 ifr[4] = {*(__half2*)&iw.x, *(__half2*)&iw.y,
                          *(__half2*)&iw.z, *(__half2*)&iw.w};
        __half2 jfr[4] = {*(__half2*)&jw.x, *(__half2*)&jw.y,
                          *(__half2*)&jw.z, *(__half2*)&jw.w};
#pragma unroll
        for (int ii = 0; ii < 4; ii++)
#pragma unroll
            for (int jj = 0; jj < 4; jj++) {
                __half2 d = __habs2(__hsub2(ifr[ii], jfr[jj]));
                if (k < 16) acc0[ii * 4 + jj] = __hfma2(d, ak, acc0[ii * 4 + jj]);
                else        acc1[ii * 4 + jj] = __hfma2(d, ak, acc1[ii * 4 + jj]);
            }
        iw = iwn;
        jw = jwn;
    }

    // ---- tmpS tile (registers, carried through the barrier) ----
    float t[16];
#pragma unroll
    for (int pp = 0; pp < 16; pp++) {
        float2 f = __half22float2(acc0[pp]);
        float2 g = __half22float2(acc1[pp]);
        float s  = (f.x + f.y) + (g.x + g.y);
        t[pp] = __expf(fmaxf(s, 0.0f));
    }

    // ---- column sums over tile-i (q-block columns) ----
    float cs[4];
#pragma unroll
    for (int jj = 0; jj < 4; jj++)
        cs[jj] = (t[0 * 4 + jj] + t[1 * 4 + jj]) + (t[2 * 4 + jj] + t[3 * 4 + jj]);
#pragma unroll
    for (int m = 4; m <= 16; m <<= 1)
#pragma unroll
        for (int jj = 0; jj < 4; jj++)
            cs[jj] += __shfl_xor_sync(0xFFFFFFFFu, cs[jj], m);
    if (r == 0)
#pragma unroll
        for (int jj = 0; jj < 4; jj++)
            cpart[wy][16 * wx + 4 * c + jj] = cs[jj];

    // ---- row sums over tile-j (p-block columns) ----
    float rs[4];
#pragma unroll
    for (int ii = 0; ii < 4; ii++)
        rs[ii] = (t[ii * 4 + 0] + t[ii * 4 + 1]) + (t[ii * 4 + 2] + t[ii * 4 + 3]);
#pragma unroll
    for (int m = 1; m <= 2; m <<= 1)
#pragma unroll
        for (int ii = 0; ii < 4; ii++)
            rs[ii] += __shfl_xor_sync(0xFFFFFFFFu, rs[ii], m);
    if (c == 0)
#pragma unroll
        for (int ii = 0; ii < 4; ii++)
            rpart[wx][32 * wy + 4 * r + ii] = rs[ii];
    __syncthreads();

    if (tid < BLK) {
        g_colpartial[n][p][BLK * q + tid] = cpart[0][tid] + cpart[1][tid];
        if (p != q)
            g_colpartial[n][q][BLK * p + tid] =
                (rpart[0][tid] + rpart[1][tid]) + (rpart[2][tid] + rpart[3][tid]);
    }

    // ========== device-wide barrier: atomic arrive, load-only spin ==========
    __threadfence();                       // publish partials
    __syncthreads();
    if (tid == 0) {
        int old = atomicAdd(&g_arrive, 1);
        if (old == NCTAS - 1) {
            atomicExch(&g_flag, 1);        // release
        } else {
            unsigned v;
            do {
                asm volatile("ld.acquire.gpu.global.u32 %0, [%1];"
                             : "=r"(v) : "l"(&g_flag));
                if (!v) __nanosleep(128);
            } while (!v);
        }
    }
    __syncthreads();
    __threadfence();                       // order post-barrier reads

    // ---- rebuild column sums for this CTA's 128 columns (L2-resident) ----
    if (tid < BLK) {
        float s = 0.0f;
#pragma unroll
        for (int b = 0; b < NBLK; b++) s += g_colpartial[n][b][BLK * q + tid];
        sinv_q[tid] = 1.0f / s;
    } else if (tid < 2 * BLK) {
        int jj = tid - BLK;
        float s = 0.0f;
#pragma unroll
        for (int b = 0; b < NBLK; b++) s += g_colpartial[n][b][BLK * p + jj];
        sinv_p[jj] = 1.0f / s;
    }
    __syncthreads();

    // ---- normalize + single write (direct tile + transpose tile) ----
    float* on = out + (size_t)n * V * V;
    const int gi0 = BLK * p + is0;
    const int gj0 = BLK * q + js0;
    const float4 invq = *(const float4*)&sinv_q[js0];
#pragma unroll
    for (int ii = 0; ii < 4; ii++) {
        float4 o = make_float4(t[ii * 4 + 0] * invq.x, t[ii * 4 + 1] * invq.y,
                               t[ii * 4 + 2] * invq.z, t[ii * 4 + 3] * invq.w);
        *(float4*)(on + (size_t)(gi0 + ii) * V + gj0) = o;
    }
    const float4 invp = *(const float4*)&sinv_p[is0];
#pragma unroll
    for (int jj = 0; jj < 4; jj++) {
        float4 o = make_float4(t[0 * 4 + jj] * invp.x, t[1 * 4 + jj] * invp.y,
                               t[2 * 4 + jj] * invp.z, t[3 * 4 + jj] * invp.w);
        *(float4*)(on + (size_t)(gj0 + jj) * V + gi0) = o;
    }

    // ---- barrier state reset by last CTA to finish (replay-safe) ----
    __syncthreads();
    if (tid == 0) {
        int old = atomicAdd(&g_done, 1);
        if (old == NCTAS - 1) {
            g_arrive = 0;
            g_flag   = 0;
            g_done   = 0;
            __threadfence();
        }
    }
}

extern "C" void kernel_launch(void* const* d_in, const int* in_sizes, int n_in,
                              void* d_out, int out_size) {
    const float* x = (const float*)d_in[0];
    const float* a = (const float*)d_in[1];
    if (n_in >= 2 && in_sizes[0] == F && in_sizes[1] == NB * TT * V * F) {
        const float* t = x; x = a; a = t;
    }
    float* out = (float*)d_out;

    dim3 g1(NPAIR, NB);
    fused_kernel<<<g1, TPB>>>(x, a, out);
}